// round 3
// baseline (speedup 1.0000x reference)
#include <cuda_runtime.h>
#include <cuda_bf16.h>
#include <cstdint>

#define M_DIM 4096
#define N_DIM 4096
#define K_DIM 2048

// ---------------- scratch (device globals; no allocations allowed) ----------------
__device__ unsigned g_minmax[4];          // [Amax_key, Amin_key, Bmax_key, Bmin_key]
__device__ float    g_q[6];               // sA, zA, sB, zB, sA*sB, fl(fl(K*zA)*zB)
__device__ float    g_rsA[M_DIM];         // rowsum(qA)  (exact integers)
__device__ float    g_csB[N_DIM];         // colsum(qB)  (exact integers)
__device__ uint8_t  g_qA [(size_t)M_DIM * K_DIM];   // qA  in u8, [M,K]
__device__ uint8_t  g_qBt[(size_t)N_DIM * K_DIM];   // qB^T in u8, [N,K]

// Monotonic unsigned key for float ordering (total order incl. negatives)
__device__ __forceinline__ unsigned fkey(float f) {
    unsigned b = __float_as_uint(f);
    return b ^ ((unsigned)((int)b >> 31) | 0x80000000u);
}
__device__ __forceinline__ float fdec(unsigned u) {
    unsigned b = (u & 0x80000000u) ? (u ^ 0x80000000u) : ~u;
    return __uint_as_float(b);
}

// ---------------- reset (scratch must be re-derived every launch) -----------------
__global__ void reset_kernel() {
    int i = blockIdx.x * blockDim.x + threadIdx.x;
    if (i < M_DIM) g_rsA[i] = 0.0f;
    if (i < N_DIM) g_csB[i] = 0.0f;
    if (i == 0) {
        g_minmax[0] = 0u;           g_minmax[1] = 0xFFFFFFFFu;
        g_minmax[2] = 0u;           g_minmax[3] = 0xFFFFFFFFu;
    }
}

// ---------------- global min/max reduction ----------------------------------------
__global__ void minmax_kernel(const float* __restrict__ x, int n4, int slot) {
    float mx = -3.402823466e38f, mn = 3.402823466e38f;
    int stride = gridDim.x * blockDim.x;
    for (int i = blockIdx.x * blockDim.x + threadIdx.x; i < n4; i += stride) {
        float4 v = reinterpret_cast<const float4*>(x)[i];
        mx = fmaxf(mx, fmaxf(fmaxf(v.x, v.y), fmaxf(v.z, v.w)));
        mn = fminf(mn, fminf(fminf(v.x, v.y), fminf(v.z, v.w)));
    }
#pragma unroll
    for (int o = 16; o; o >>= 1) {
        mx = fmaxf(mx, __shfl_xor_sync(0xFFFFFFFFu, mx, o));
        mn = fminf(mn, __shfl_xor_sync(0xFFFFFFFFu, mn, o));
    }
    __shared__ float smx[8], smn[8];
    int w = threadIdx.x >> 5;
    if ((threadIdx.x & 31) == 0) { smx[w] = mx; smn[w] = mn; }
    __syncthreads();
    if (threadIdx.x == 0) {
#pragma unroll
        for (int j = 1; j < 8; j++) { mx = fmaxf(mx, smx[j]); mn = fminf(mn, smn[j]); }
        atomicMax(&g_minmax[slot],     fkey(mx));
        atomicMin(&g_minmax[slot + 1], fkey(mn));
    }
}

// ---------------- quant params (replicates reference fp32 ops exactly) ------------
__global__ void qparams_kernel() {
    float amax = fdec(g_minmax[0]), amin = fdec(g_minmax[1]);
    float bmax = fdec(g_minmax[2]), bmin = fdec(g_minmax[3]);
    float sA = __fdiv_rn(__fadd_rn(amax, -amin), 255.0f);
    float zA = rintf(__fdiv_rn(-amin, sA));
    float sB = __fdiv_rn(__fadd_rn(bmax, -bmin), 255.0f);
    float zB = rintf(__fdiv_rn(-bmin, sB));
    g_q[0] = sA; g_q[1] = zA; g_q[2] = sB; g_q[3] = zB;
    g_q[4] = __fmul_rn(sA, sB);
    g_q[5] = __fmul_rn(__fmul_rn((float)K_DIM, zA), zB);   // fl(fl(K*zA)*zB)
}

__device__ __forceinline__ float quant1(float v, float s, float z) {
    float q = __fadd_rn(rintf(__fdiv_rn(v, s)), z);
    return fminf(fmaxf(q, 0.0f), 255.0f);
}

// ---------------- quantize A -> u8 + rowsums --------------------------------------
// One thread handles 8 consecutive elements (same row); warp = 256 elems, same row.
__global__ void quantA_kernel(const float* __restrict__ A) {
    const float sA = g_q[0], zA = g_q[1];
    int t = blockIdx.x * blockDim.x + threadIdx.x;
    int base = t * 8;
    float4 v0 = *reinterpret_cast<const float4*>(A + base);
    float4 v1 = *reinterpret_cast<const float4*>(A + base + 4);
    float q[8];
    q[0] = quant1(v0.x, sA, zA); q[1] = quant1(v0.y, sA, zA);
    q[2] = quant1(v0.z, sA, zA); q[3] = quant1(v0.w, sA, zA);
    q[4] = quant1(v1.x, sA, zA); q[5] = quant1(v1.y, sA, zA);
    q[6] = quant1(v1.z, sA, zA); q[7] = quant1(v1.w, sA, zA);
    float rsum = 0.0f;
#pragma unroll
    for (int j = 0; j < 8; j++) rsum += q[j];          // exact (small ints)
    uint2 pk;
    pk.x = (unsigned)q[0] | ((unsigned)q[1] << 8) | ((unsigned)q[2] << 16) | ((unsigned)q[3] << 24);
    pk.y = (unsigned)q[4] | ((unsigned)q[5] << 8) | ((unsigned)q[6] << 16) | ((unsigned)q[7] << 24);
    *reinterpret_cast<uint2*>(g_qA + base) = pk;
#pragma unroll
    for (int o = 16; o; o >>= 1) rsum += __shfl_xor_sync(0xFFFFFFFFu, rsum, o);
    if ((threadIdx.x & 31) == 0) atomicAdd(&g_rsA[base >> 11], rsum);  // base/2048
}

// ---------------- quantize + transpose B -> Bt[N,K] u8 + colsums ------------------
// Block: 32x8 threads, tile 32x32.
__global__ void quantB_kernel(const float* __restrict__ B) {
    __shared__ float tile[32][33];
    __shared__ float psum[8][32];
    const float sB = g_q[2], zB = g_q[3];
    int n0 = blockIdx.x * 32, k0 = blockIdx.y * 32;
    int tx = threadIdx.x, ty = threadIdx.y;
    float part = 0.0f;
#pragma unroll
    for (int i = 0; i < 4; i++) {
        int k = k0 + ty + i * 8;
        float v = B[(size_t)k * N_DIM + (n0 + tx)];
        float q = quant1(v, sB, zB);
        tile[ty + i * 8][tx] = q;
        part += q;
    }
    psum[ty][tx] = part;
    __syncthreads();
    if (ty == 0) {
        float s = 0.0f;
#pragma unroll
        for (int j = 0; j < 8; j++) s += psum[j][tx];
        atomicAdd(&g_csB[n0 + tx], s);                 // exact ints -> order-free
    }
    // write phase: linear tid; each thread writes one uchar4 (4 consecutive k)
    int tid = ty * 32 + tx;
    int n_local = tid >> 3;          // 0..31
    int kc = (tid & 7) * 4;          // 0,4,...,28
    uchar4 o;
    o.x = (uint8_t)tile[kc + 0][n_local];
    o.y = (uint8_t)tile[kc + 1][n_local];
    o.z = (uint8_t)tile[kc + 2][n_local];
    o.w = (uint8_t)tile[kc + 3][n_local];
    *reinterpret_cast<uchar4*>(g_qBt + (size_t)(n0 + n_local) * K_DIM + k0 + kc) = o;
}

// ---------------- GEMM: acc = qA @ qB (u8 x u8 -> s32, exact) ---------------------
// CTA tile 128x128, BK=64 bytes, 4-stage cp.async ring, 8 warps (2x4), warp 64x32.
#define LDT 80                    // smem row stride in BYTES (64 data + 16 pad)
#define STAGES 4
#define TILEB (128 * LDT)         // bytes per (A or B) stage

__global__ __launch_bounds__(256, 2) void gemm_kernel(float* __restrict__ out) {
    extern __shared__ uint8_t smem[];
    const int tid = threadIdx.x;
    const int lane = tid & 31, warp = tid >> 5;
    const int wm = warp >> 2, wn = warp & 3;           // 2x4 warp grid
    const int m0 = blockIdx.y * 128, n0 = blockIdx.x * 128;

    int acc[4][4][4];
#pragma unroll
    for (int i = 0; i < 4; i++)
#pragma unroll
        for (int j = 0; j < 4; j++)
#pragma unroll
            for (int e = 0; e < 4; e++) acc[i][j][e] = 0;

    unsigned sA0 = (unsigned)__cvta_generic_to_shared(smem);
    unsigned sB0 = sA0 + STAGES * TILEB;
    const int crow = tid >> 2;          // 0..63
    const int ccol = (tid & 3) * 16;    // byte offset within 64B k-chunk

#define COPY_TILE(stage, kt)                                                           \
    do {                                                                               \
        _Pragma("unroll")                                                              \
        for (int r = 0; r < 2; ++r) {                                                  \
            int row = crow + r * 64;                                                   \
            unsigned da = sA0 + (unsigned)((stage) * TILEB + row * LDT + ccol);        \
            const void* pa = g_qA + (size_t)(m0 + row) * K_DIM + (kt) * 64 + ccol;     \
            asm volatile("cp.async.cg.shared.global [%0], [%1], 16;" :: "r"(da), "l"(pa)); \
            unsigned db = sB0 + (unsigned)((stage) * TILEB + row * LDT + ccol);        \
            const void* pb = g_qBt + (size_t)(n0 + row) * K_DIM + (kt) * 64 + ccol;    \
            asm volatile("cp.async.cg.shared.global [%0], [%1], 16;" :: "r"(db), "l"(pb)); \
        }                                                                              \
    } while (0)

    const int NT = K_DIM / 64;   // 32
#pragma unroll
    for (int s = 0; s < STAGES - 1; ++s) {
        COPY_TILE(s, s);
        asm volatile("cp.async.commit_group;");
    }

    for (int kt = 0; kt < NT; ++kt) {
        asm volatile("cp.async.wait_group %0;" :: "n"(STAGES - 2));
        __syncthreads();
        // prefetch stage kt+STAGES-1 into the buffer just freed by iter kt-1
        if (kt + STAGES - 1 < NT) COPY_TILE((kt + STAGES - 1) & (STAGES - 1), kt + STAGES - 1);
        asm volatile("cp.async.commit_group;");

        int buf = kt & (STAGES - 1);
        unsigned aBase = sA0 + (unsigned)(buf * TILEB);
        unsigned bBase = sB0 + (unsigned)(buf * TILEB);
#pragma unroll
        for (int ks = 0; ks < 2; ++ks) {                // two k=32 chunks per stage
            unsigned a[4][4];
#pragma unroll
            for (int mi = 0; mi < 4; mi++) {
                int arow = wm * 64 + mi * 16 + (lane & 7) + ((lane >> 3) & 1) * 8;
                int acol = ks * 32 + ((lane >> 4) & 1) * 16;   // bytes
                unsigned addr = aBase + (unsigned)(arow * LDT + acol);
                asm volatile("ldmatrix.sync.aligned.m8n8.x4.shared.b16 {%0,%1,%2,%3}, [%4];"
                             : "=r"(a[mi][0]), "=r"(a[mi][1]), "=r"(a[mi][2]), "=r"(a[mi][3])
                             : "r"(addr));
            }
            unsigned b[8];
#pragma unroll
            for (int nj = 0; nj < 2; nj++) {
                int brow = wn * 32 + nj * 16 + (lane & 7) + ((lane >> 4) & 1) * 8;
                int bcol = ks * 32 + ((lane >> 3) & 1) * 16;   // bytes
                unsigned addr = bBase + (unsigned)(brow * LDT + bcol);
                asm volatile("ldmatrix.sync.aligned.m8n8.x4.shared.b16 {%0,%1,%2,%3}, [%4];"
                             : "=r"(b[nj * 4 + 0]), "=r"(b[nj * 4 + 1]),
                               "=r"(b[nj * 4 + 2]), "=r"(b[nj * 4 + 3])
                             : "r"(addr));
            }
#pragma unroll
            for (int mi = 0; mi < 4; mi++)
#pragma unroll
                for (int ni = 0; ni < 4; ni++) {
                    unsigned b0 = b[(ni >> 1) * 4 + (ni & 1) * 2];
                    unsigned b1 = b[(ni >> 1) * 4 + (ni & 1) * 2 + 1];
                    asm volatile(
                        "mma.sync.aligned.m16n8k32.row.col.s32.u8.u8.s32 "
                        "{%0,%1,%2,%3},{%4,%5,%6,%7},{%8,%9},{%0,%1,%2,%3};"
                        : "+r"(acc[mi][ni][0]), "+r"(acc[mi][ni][1]),
                          "+r"(acc[mi][ni][2]), "+r"(acc[mi][ni][3])
                        : "r"(a[mi][0]), "r"(a[mi][1]), "r"(a[mi][2]), "r"(a[mi][3]),
                          "r"(b0), "r"(b1));
                }
        }
    }

    // Epilogue: acc is the EXACT int32 qA@qB. Replay the reference fp32 sequence.
    const float zA = g_q[1], zB = g_q[3], s = g_q[4], kzz = g_q[5];
    const int gid = lane >> 2, tig = lane & 3;
#pragma unroll
    for (int mi = 0; mi < 4; mi++) {
#pragma unroll
        for (int ni = 0; ni < 4; ni++) {
            int row0 = m0 + wm * 64 + mi * 16 + gid;
            int col0 = n0 + wn * 32 + ni * 8 + tig * 2;
            float csf0 = g_csB[col0], csf1 = g_csB[col0 + 1];
#pragma unroll
            for (int h = 0; h < 2; h++) {              // row, row+8
                int row = row0 + h * 8;
                float rsf = g_rsA[row];
                float v[2];
#pragma unroll
                for (int c = 0; c < 2; c++) {
                    float accf = (float)acc[mi][ni][h * 2 + c];   // int32 -> f32 (RN), matches jnp
                    float csf  = c ? csf1 : csf0;
                    float t = __fadd_rn(accf, -__fmul_rn(zA, csf));
                    t = __fadd_rn(t, -__fmul_rn(zB, rsf));
                    t = __fadd_rn(t, kzz);
                    v[c] = __fmul_rn(s, t);
                }
                *reinterpret_cast<float2*>(out + (size_t)row * N_DIM + col0) =
                    make_float2(v[0], v[1]);
            }
        }
    }
}

// ---------------- launch ----------------------------------------------------------
extern "C" void kernel_launch(void* const* d_in, const int* in_sizes, int n_in,
                              void* d_out, int out_size) {
    const float* A = (const float*)d_in[0];
    const float* B = (const float*)d_in[1];
    float* out = (float*)d_out;

    static const int GEMM_SMEM = 2 * STAGES * TILEB;   // 81920 bytes
    cudaFuncSetAttribute(gemm_kernel, cudaFuncAttributeMaxDynamicSharedMemorySize, GEMM_SMEM);

    reset_kernel<<<16, 256>>>();
    minmax_kernel<<<1024, 256>>>(A, (M_DIM * K_DIM) / 4, 0);
    minmax_kernel<<<1024, 256>>>(B, (K_DIM * N_DIM) / 4, 2);
    qparams_kernel<<<1, 1>>>();
    quantA_kernel<<<(M_DIM * K_DIM) / (256 * 8), 256>>>(A);
    quantB_kernel<<<dim3(N_DIM / 32, K_DIM / 32), dim3(32, 8)>>>(B);
    gemm_kernel<<<dim3(N_DIM / 128, M_DIM / 128), 256, GEMM_SMEM>>>(out);
}

// round 7
// speedup vs baseline: 1.9898x; 1.9898x over previous
#include <cuda_runtime.h>
#include <cuda_bf16.h>
#include <cstdint>

#define M_DIM 4096
#define N_DIM 4096
#define K_DIM 2048

// ---------------- scratch (device globals; no allocations allowed) ----------------
__device__ unsigned g_minmax[4];
__device__ float    g_q[6];               // sA, zA, sB, zB, sA*sB, fl(fl(K*zA)*zB)
__device__ float    g_rsA[M_DIM];         // rowsum(qA)  (exact integers)
__device__ float    g_csB[N_DIM];         // colsum(qB)  (exact integers)
__device__ __nv_bfloat16 g_qA [(size_t)M_DIM * K_DIM];   // (qA - zA), exact ints in bf16
__device__ __nv_bfloat16 g_qBt[(size_t)N_DIM * K_DIM];   // (qB - zB)^T  [N,K]

__device__ __forceinline__ unsigned fkey(float f) {
    unsigned b = __float_as_uint(f);
    return b ^ ((unsigned)((int)b >> 31) | 0x80000000u);
}
__device__ __forceinline__ float fdec(unsigned u) {
    unsigned b = (u & 0x80000000u) ? (u ^ 0x80000000u) : ~u;
    return __uint_as_float(b);
}

// ---------------- reset ------------------------------------------------------------
__global__ void reset_kernel() {
    int i = blockIdx.x * blockDim.x + threadIdx.x;
    if (i < M_DIM) g_rsA[i] = 0.0f;
    if (i < N_DIM) g_csB[i] = 0.0f;
    if (i == 0) {
        g_minmax[0] = 0u;           g_minmax[1] = 0xFFFFFFFFu;
        g_minmax[2] = 0u;           g_minmax[3] = 0xFFFFFFFFu;
    }
}

// ---------------- global min/max ---------------------------------------------------
__global__ void minmax_kernel(const float* __restrict__ x, int n4, int slot) {
    float mx = -3.402823466e38f, mn = 3.402823466e38f;
    int stride = gridDim.x * blockDim.x;
    for (int i = blockIdx.x * blockDim.x + threadIdx.x; i < n4; i += stride) {
        float4 v = reinterpret_cast<const float4*>(x)[i];
        mx = fmaxf(mx, fmaxf(fmaxf(v.x, v.y), fmaxf(v.z, v.w)));
        mn = fminf(mn, fminf(fminf(v.x, v.y), fminf(v.z, v.w)));
    }
#pragma unroll
    for (int o = 16; o; o >>= 1) {
        mx = fmaxf(mx, __shfl_xor_sync(0xFFFFFFFFu, mx, o));
        mn = fminf(mn, __shfl_xor_sync(0xFFFFFFFFu, mn, o));
    }
    __shared__ float smx[8], smn[8];
    int w = threadIdx.x >> 5;
    if ((threadIdx.x & 31) == 0) { smx[w] = mx; smn[w] = mn; }
    __syncthreads();
    if (threadIdx.x == 0) {
#pragma unroll
        for (int j = 1; j < 8; j++) { mx = fmaxf(mx, smx[j]); mn = fminf(mn, smn[j]); }
        atomicMax(&g_minmax[slot],     fkey(mx));
        atomicMin(&g_minmax[slot + 1], fkey(mn));
    }
}

// ---------------- quant params (replicates reference fp32 ops exactly) -------------
__global__ void qparams_kernel() {
    float amax = fdec(g_minmax[0]), amin = fdec(g_minmax[1]);
    float bmax = fdec(g_minmax[2]), bmin = fdec(g_minmax[3]);
    float sA = __fdiv_rn(__fadd_rn(amax, -amin), 255.0f);
    float zA = rintf(__fdiv_rn(-amin, sA));
    float sB = __fdiv_rn(__fadd_rn(bmax, -bmin), 255.0f);
    float zB = rintf(__fdiv_rn(-bmin, sB));
    g_q[0] = sA; g_q[1] = zA; g_q[2] = sB; g_q[3] = zB;
    g_q[4] = __fmul_rn(sA, sB);
    g_q[5] = __fmul_rn(__fmul_rn((float)K_DIM, zA), zB);
}

__device__ __forceinline__ float quant1(float v, float s, float z) {
    float q = __fadd_rn(rintf(__fdiv_rn(v, s)), z);
    return fminf(fmaxf(q, 0.0f), 255.0f);
}
__device__ __forceinline__ unsigned pack_bf2(float lo, float hi) {
    unsigned a = (unsigned)__bfloat16_as_ushort(__float2bfloat16_rn(lo));
    unsigned b = (unsigned)__bfloat16_as_ushort(__float2bfloat16_rn(hi));
    return a | (b << 16);
}

// ---------------- fused quantize A (centered bf16 + rowsums) and B (transpose) -----
#define GA_BLOCKS ((M_DIM * K_DIM) / (256 * 8))        // 4096
#define GB_BLOCKS ((N_DIM / 32) * (K_DIM / 32))        // 8192

__global__ void quantAB_kernel(const float* __restrict__ A, const float* __restrict__ B) {
    __shared__ float tile[32][33];
    __shared__ float psum[8][32];
    if (blockIdx.x < GA_BLOCKS) {
        const float sA = g_q[0], zA = g_q[1];
        int t = blockIdx.x * blockDim.x + threadIdx.x;
        int base = t * 8;
        float4 v0 = *reinterpret_cast<const float4*>(A + base);
        float4 v1 = *reinterpret_cast<const float4*>(A + base + 4);
        float q[8];
        q[0] = quant1(v0.x, sA, zA); q[1] = quant1(v0.y, sA, zA);
        q[2] = quant1(v0.z, sA, zA); q[3] = quant1(v0.w, sA, zA);
        q[4] = quant1(v1.x, sA, zA); q[5] = quant1(v1.y, sA, zA);
        q[6] = quant1(v1.z, sA, zA); q[7] = quant1(v1.w, sA, zA);
        float rsum = 0.0f;
#pragma unroll
        for (int j = 0; j < 8; j++) rsum += q[j];
        uint4 pk;
        pk.x = pack_bf2(q[0] - zA, q[1] - zA);
        pk.y = pack_bf2(q[2] - zA, q[3] - zA);
        pk.z = pack_bf2(q[4] - zA, q[5] - zA);
        pk.w = pack_bf2(q[6] - zA, q[7] - zA);
        *reinterpret_cast<uint4*>(g_qA + base) = pk;
#pragma unroll
        for (int o = 16; o; o >>= 1) rsum += __shfl_xor_sync(0xFFFFFFFFu, rsum, o);
        if ((threadIdx.x & 31) == 0) atomicAdd(&g_rsA[base >> 11], rsum);
    } else {
        const float sB = g_q[2], zB = g_q[3];
        int bid2 = blockIdx.x - GA_BLOCKS;
        int n0 = (bid2 & 127) * 32, k0 = (bid2 >> 7) * 32;
        int tx = threadIdx.x & 31, ty = threadIdx.x >> 5;
        float part = 0.0f;
#pragma unroll
        for (int i = 0; i < 4; i++) {
            int k = k0 + ty + i * 8;
            float v = B[(size_t)k * N_DIM + (n0 + tx)];
            float q = quant1(v, sB, zB);
            tile[ty + i * 8][tx] = q;
            part += q;
        }
        psum[ty][tx] = part;
        __syncthreads();
        if (ty == 0) {
            float s = 0.0f;
#pragma unroll
            for (int j = 0; j < 8; j++) s += psum[j][tx];
            atomicAdd(&g_csB[n0 + tx], s);
        }
#pragma unroll
        for (int i = 0; i < 4; i++) {
            int n = n0 + ty + i * 8;
            float q = tile[tx][ty + i * 8];
            g_qBt[(size_t)n * K_DIM + (k0 + tx)] = __float2bfloat16_rn(q - zB);
        }
    }
}

// ---------------- GEMM: D = (qA-zA) @ (qB-zB)^T, bf16 HMMA, fp32 accum (exact) -----
// CTA tile 128x128, BK=64, 3-stage cp.async ring, one barrier per 64-k iter.
#define LDT 72                      // smem row stride in bf16 elems (144B): conflict-free
#define STAGES 3
#define TILEE (128 * LDT)           // elems per (A or B) stage
#define GEMM_SMEM (2 * STAGES * TILEE * 2)   // bytes = 110592
#define NT (K_DIM / 64)             // 32

__global__ __launch_bounds__(256, 2) void gemm_kernel(float* __restrict__ out) {
    extern __shared__ __nv_bfloat16 smem[];
    const int tid = threadIdx.x;
    const int lane = tid & 31, warp = tid >> 5;
    const int wm = warp >> 2, wn = warp & 3;           // 2x4 warp grid, warp tile 64x32
    const int m0 = blockIdx.y * 128, n0 = blockIdx.x * 128;

    float acc[4][4][4];
#pragma unroll
    for (int i = 0; i < 4; i++)
#pragma unroll
        for (int j = 0; j < 4; j++)
#pragma unroll
            for (int e = 0; e < 4; e++) acc[i][j][e] = 0.0f;

    unsigned sA0 = (unsigned)__cvta_generic_to_shared(smem);
    unsigned sB0 = sA0 + STAGES * TILEE * 2;

    // A/B stage fill: 128 rows x 64 bf16 = 128B/row = 8 chunks of 16B per row.
    // 1024 chunks per tensor per stage -> 4 per thread per tensor.
#define FILL(stage, kt)                                                                 \
    do {                                                                                \
        _Pragma("unroll")                                                               \
        for (int p = 0; p < 4; ++p) {                                                   \
            int cid = tid + p * 256;            /* 0..1023 */                           \
            int row = cid >> 3, ch = cid & 7;   /* 128 rows x 8 chunks */               \
            unsigned da = sA0 + (unsigned)((stage) * TILEE + row * LDT + ch * 8) * 2;   \
            const void* pa = g_qA + (size_t)(m0 + row) * K_DIM + (kt) * 64 + ch * 8;    \
            asm volatile("cp.async.cg.shared.global [%0], [%1], 16;" :: "r"(da), "l"(pa)); \
            unsigned db = sB0 + (unsigned)((stage) * TILEE + row * LDT + ch * 8) * 2;   \
            const void* pb = g_qBt + (size_t)(n0 + row) * K_DIM + (kt) * 64 + ch * 8;   \
            asm volatile("cp.async.cg.shared.global [%0], [%1], 16;" :: "r"(db), "l"(pb)); \
        }                                                                               \
        asm volatile("cp.async.commit_group;");                                         \
    } while (0)

#pragma unroll
    for (int s = 0; s < STAGES - 1; ++s) FILL(s, s);

    for (int kt = 0; kt < NT; ++kt) {
        if (kt <= NT - STAGES) asm volatile("cp.async.wait_group %0;" :: "n"(STAGES - 2));
        else                   asm volatile("cp.async.wait_group 0;");
        __syncthreads();
        if (kt + STAGES - 1 < NT) FILL((kt + STAGES - 1) % STAGES, kt + STAGES - 1);

        int buf = kt % STAGES;
        unsigned aBase = sA0 + (unsigned)(buf * TILEE) * 2;
        unsigned bBase = sB0 + (unsigned)(buf * TILEE) * 2;
#pragma unroll
        for (int ks = 0; ks < 4; ++ks) {                // four k=16 chunks per stage
            unsigned a[4][4];
#pragma unroll
            for (int mi = 0; mi < 4; mi++) {
                int arow = wm * 64 + mi * 16 + (lane & 7) + ((lane >> 3) & 1) * 8;
                int acol = ks * 16 + ((lane >> 4) & 1) * 8;
                unsigned addr = aBase + (unsigned)(arow * LDT + acol) * 2;
                asm volatile("ldmatrix.sync.aligned.m8n8.x4.shared.b16 {%0,%1,%2,%3}, [%4];"
                             : "=r"(a[mi][0]), "=r"(a[mi][1]), "=r"(a[mi][2]), "=r"(a[mi][3])
                             : "r"(addr));
            }
            unsigned b[8];
#pragma unroll
            for (int nj = 0; nj < 2; nj++) {
                int brow = wn * 32 + nj * 16 + (lane & 7) + ((lane >> 4) & 1) * 8;
                int bcol = ks * 16 + ((lane >> 3) & 1) * 8;
                unsigned addr = bBase + (unsigned)(brow * LDT + bcol) * 2;
                asm volatile("ldmatrix.sync.aligned.m8n8.x4.shared.b16 {%0,%1,%2,%3}, [%4];"
                             : "=r"(b[nj * 4 + 0]), "=r"(b[nj * 4 + 1]),
                               "=r"(b[nj * 4 + 2]), "=r"(b[nj * 4 + 3])
                             : "r"(addr));
            }
#pragma unroll
            for (int mi = 0; mi < 4; mi++)
#pragma unroll
                for (int ni = 0; ni < 4; ni++) {
                    unsigned b0 = b[(ni >> 1) * 4 + (ni & 1) * 2];
                    unsigned b1 = b[(ni >> 1) * 4 + (ni & 1) * 2 + 1];
                    asm volatile(
                        "mma.sync.aligned.m16n8k16.row.col.f32.bf16.bf16.f32 "
                        "{%0,%1,%2,%3},{%4,%5,%6,%7},{%8,%9},{%0,%1,%2,%3};"
                        : "+f"(acc[mi][ni][0]), "+f"(acc[mi][ni][1]),
                          "+f"(acc[mi][ni][2]), "+f"(acc[mi][ni][3])
                        : "r"(a[mi][0]), "r"(a[mi][1]), "r"(a[mi][2]), "r"(a[mi][3]),
                          "r"(b0), "r"(b1));
                }
        }
    }

    // Epilogue: reconstruct reference's exact fp32 rounding sequence.
    const float zA = g_q[1], zB = g_q[3], s = g_q[4], kzz = g_q[5];
    const int izA = (int)zA, izB = (int)zB;
    const long long kii = (long long)K_DIM * (long long)izA * (long long)izB;
    const int gid = lane >> 2, tig = lane & 3;
#pragma unroll
    for (int mi = 0; mi < 4; mi++) {
#pragma unroll
        for (int ni = 0; ni < 4; ni++) {
            int row0 = m0 + wm * 64 + mi * 16 + gid;
            int col0 = n0 + wn * 32 + ni * 8 + tig * 2;
            float csf0 = g_csB[col0], csf1 = g_csB[col0 + 1];
#pragma unroll
            for (int h = 0; h < 2; h++) {
                int row = row0 + h * 8;
                float rsf = g_rsA[row];
                float v[2];
#pragma unroll
                for (int c = 0; c < 2; c++) {
                    float D   = acc[mi][ni][h * 2 + c];            // exact integer
                    float csf = c ? csf1 : csf0;
                    long long ai = (long long)llrintf(D)
                                 + (long long)izA * (long long)__float2int_rn(csf)
                                 + (long long)izB * (long long)__float2int_rn(rsf)
                                 - kii;
                    float accf = (float)ai;                        // == jnp int32->f32 cast
                    float t = __fadd_rn(accf, -__fmul_rn(zA, csf));
                    t = __fadd_rn(t, -__fmul_rn(zB, rsf));
                    t = __fadd_rn(t, kzz);
                    v[c] = __fmul_rn(s, t);
                }
                *reinterpret_cast<float2*>(out + (size_t)row * N_DIM + col0) =
                    make_float2(v[0], v[1]);
            }
        }
    }
}

// ---------------- launch -----------------------------------------------------------
extern "C" void kernel_launch(void* const* d_in, const int* in_sizes, int n_in,
                              void* d_out, int out_size) {
    const float* A = (const float*)d_in[0];
    const float* B = (const float*)d_in[1];
    float* out = (float*)d_out;

    cudaFuncSetAttribute(gemm_kernel, cudaFuncAttributeMaxDynamicSharedMemorySize, GEMM_SMEM);

    reset_kernel<<<16, 256>>>();
    minmax_kernel<<<1024, 256>>>(A, (M_DIM * K_DIM) / 4, 0);
    minmax_kernel<<<1024, 256>>>(B, (K_DIM * N_DIM) / 4, 2);
    qparams_kernel<<<1, 1>>>();
    quantAB_kernel<<<GA_BLOCKS + GB_BLOCKS, 256>>>(A, B);
    gemm_kernel<<<dim3(N_DIM / 128, M_DIM / 128), 256, GEMM_SMEM>>>(out);
}